// round 1
// baseline (speedup 1.0000x reference)
#include <cuda_runtime.h>
#include <math.h>

#define NN 50000
#define EE 400000
#define D_IN 128
#define D_HID 128
#define D_OUT 64

// ---------------- scratch (static device globals; no allocation allowed) ----------------
__device__ float g_Q0[4][NN * D_HID];
__device__ float g_K0[4][NN * D_HID];
__device__ float g_V0[4][NN * D_HID];
__device__ float g_H[NN * D_HID];
__device__ float g_Q1[2][NN * D_OUT];
__device__ float g_K1[2][NN * D_OUT];
__device__ float g_V1[2][NN * D_OUT];
__device__ int g_deg[NN];
__device__ int g_cursor[NN];
__device__ int g_rowptr[2][NN + 1];
__device__ int g_cols[2][EE];

// ---------------- CSR build ----------------
__global__ void zero_deg_kernel(int n) {
    int i = blockIdx.x * blockDim.x + threadIdx.x;
    if (i < n) g_deg[i] = 0;
}

__global__ void count_deg_kernel(const int* __restrict__ rows, int e) {
    int i = blockIdx.x * blockDim.x + threadIdx.x;
    if (i < e) atomicAdd(&g_deg[rows[i]], 1);
}

// single-block exclusive scan over g_deg -> g_rowptr[hop]
__global__ void scan_kernel(int hop, int n) {
    __shared__ int sm[1024];
    __shared__ int carry;
    if (threadIdx.x == 0) carry = 0;
    __syncthreads();
    for (int base = 0; base < n; base += 1024) {
        int i = base + threadIdx.x;
        int v = (i < n) ? g_deg[i] : 0;
        sm[threadIdx.x] = v;
        __syncthreads();
        for (int off = 1; off < 1024; off <<= 1) {
            int t = (threadIdx.x >= off) ? sm[threadIdx.x - off] : 0;
            __syncthreads();
            sm[threadIdx.x] += t;
            __syncthreads();
        }
        if (i < n) g_rowptr[hop][i] = carry + sm[threadIdx.x] - v;
        __syncthreads();
        if (threadIdx.x == 0) carry += sm[1023];
        __syncthreads();
    }
    if (threadIdx.x == 0) g_rowptr[hop][n] = carry;
}

__global__ void cursor_kernel(int hop, int n) {
    int i = blockIdx.x * blockDim.x + threadIdx.x;
    if (i < n) g_cursor[i] = g_rowptr[hop][i];
}

__global__ void scatter_kernel(const int* __restrict__ rows, const int* __restrict__ cols,
                               int e, int hop) {
    int i = blockIdx.x * blockDim.x + threadIdx.x;
    if (i < e) {
        int r = rows[i];
        int p = atomicAdd(&g_cursor[r], 1);
        g_cols[hop][p] = cols[i];
    }
}

// ---------------- batched QKV GEMM (one launch per layer, blockIdx.z = combo*3 + {q,k,v}) ----------------
template <int LAYER, int BM, int BN, int BK, int TM, int TN>
__global__ void __launch_bounds__(256) qkv_gemm_kernel(
    const float* __restrict__ Xin,
    const float* __restrict__ Wq, const float* __restrict__ Wk, const float* __restrict__ Wv,
    const float* __restrict__ bq, const float* __restrict__ bk, const float* __restrict__ bv,
    int M, int Kd) {
    constexpr int THREADS = (BM / TM) * (BN / TN);
    const float* X = (LAYER == 0) ? Xin : (const float*)g_H;
    int z = blockIdx.z;
    int c = z / 3, mm = z % 3;
    const float* W = (mm == 0 ? Wq : (mm == 1 ? Wk : Wv)) + (size_t)c * Kd * BN;
    const float* bias = (mm == 0 ? bq : (mm == 1 ? bk : bv)) + (size_t)c * BN;
    float* O;
    if (LAYER == 0) O = (mm == 0 ? g_Q0[c] : (mm == 1 ? g_K0[c] : g_V0[c]));
    else            O = (mm == 0 ? g_Q1[c] : (mm == 1 ? g_K1[c] : g_V1[c]));

    __shared__ float As[BK][BM + 4];
    __shared__ float Bs[BK][BN];
    int tid = threadIdx.x;
    int tx = tid % (BN / TN);
    int ty = tid / (BN / TN);
    int row0 = blockIdx.x * BM;

    float acc[TM][TN];
#pragma unroll
    for (int i = 0; i < TM; i++)
#pragma unroll
        for (int j = 0; j < TN; j++) acc[i][j] = 0.f;

    constexpr int APR = BK / 4;  // float4 slots per A row
    constexpr int BPR = BN / 4;  // float4 slots per B row

    for (int k0 = 0; k0 < Kd; k0 += BK) {
#pragma unroll
        for (int r = tid / APR; r < BM; r += THREADS / APR) {
            int kc = (tid % APR) * 4;
            int gr = row0 + r;
            float4 a = (gr < M) ? *(const float4*)(X + (size_t)gr * Kd + k0 + kc)
                                : make_float4(0.f, 0.f, 0.f, 0.f);
            As[kc + 0][r] = a.x; As[kc + 1][r] = a.y;
            As[kc + 2][r] = a.z; As[kc + 3][r] = a.w;
        }
#pragma unroll
        for (int r = tid / BPR; r < BK; r += (THREADS / BPR > 0 ? THREADS / BPR : 1)) {
            int nc = (tid % BPR) * 4;
            *(float4*)&Bs[r][nc] = *(const float4*)(W + (size_t)(k0 + r) * BN + nc);
        }
        __syncthreads();
#pragma unroll
        for (int kk = 0; kk < BK; kk++) {
            float ra[TM], rb[TN];
#pragma unroll
            for (int i = 0; i < TM; i++) ra[i] = As[kk][ty * TM + i];
#pragma unroll
            for (int j = 0; j < TN; j++) rb[j] = Bs[kk][tx * TN + j];
#pragma unroll
            for (int i = 0; i < TM; i++)
#pragma unroll
                for (int j = 0; j < TN; j++) acc[i][j] += ra[i] * rb[j];
        }
        __syncthreads();
    }
#pragma unroll
    for (int i = 0; i < TM; i++) {
        int gr = row0 + ty * TM + i;
        if (gr < M) {
#pragma unroll
            for (int j = 0; j < TN; j += 4) {
                int col = tx * TN + j;
                float4 o;
                o.x = acc[i][j + 0] + bias[col + 0];
                o.y = acc[i][j + 1] + bias[col + 1];
                o.z = acc[i][j + 2] + bias[col + 2];
                o.w = acc[i][j + 3] + bias[col + 3];
                *(float4*)(O + (size_t)gr * BN + col) = o;
            }
        }
    }
}

// ---------------- warp-per-row sparse attention with online softmax ----------------
// VEC=4 -> D=128, 4 heads of 32 dims (8 lanes/head). VEC=2 -> D=64, 4 heads of 16 dims.
template <int VEC>
__global__ void attn_kernel(int combo, int hop, float beta, float scale, int accumulate,
                            float* __restrict__ out_ext, int use_ext, int n) {
    int gw = (blockIdx.x * blockDim.x + threadIdx.x) >> 5;
    if (gw >= n) return;
    int lane = threadIdx.x & 31;
    const int D = VEC * 32;
    const float* Q; const float* Kp; const float* Vp;
    if (VEC == 4) { Q = g_Q0[combo]; Kp = g_K0[combo]; Vp = g_V0[combo]; }
    else          { Q = g_Q1[combo]; Kp = g_K1[combo]; Vp = g_V1[combo]; }
    float* out = use_ext ? out_ext : (float*)g_H;

    float q[VEC], acc[VEC];
    {
        const float* qp = Q + (size_t)gw * D + lane * VEC;
        if (VEC == 4) { float4 t = *(const float4*)qp; q[0]=t.x; q[1]=t.y; q[2]=t.z; q[3]=t.w; }
        else          { float2 t = *(const float2*)qp; q[0]=t.x; q[1]=t.y; }
    }
#pragma unroll
    for (int v = 0; v < VEC; v++) acc[v] = 0.f;
    float m = -INFINITY, l = 0.f;

    int s0 = g_rowptr[hop][gw], s1 = g_rowptr[hop][gw + 1];
    for (int p = s0; p < s1; p++) {
        int cidx = g_cols[hop][p];
        float kx[VEC];
        {
            const float* kp = Kp + (size_t)cidx * D + lane * VEC;
            if (VEC == 4) { float4 t = *(const float4*)kp; kx[0]=t.x; kx[1]=t.y; kx[2]=t.z; kx[3]=t.w; }
            else          { float2 t = *(const float2*)kp; kx[0]=t.x; kx[1]=t.y; }
        }
        float dot = 0.f;
#pragma unroll
        for (int v = 0; v < VEC; v++) dot += q[v] * kx[v];
        // reduce within 8-lane head group
        dot += __shfl_xor_sync(0xffffffffu, dot, 1);
        dot += __shfl_xor_sync(0xffffffffu, dot, 2);
        dot += __shfl_xor_sync(0xffffffffu, dot, 4);
        float s = dot * scale;
        float nm = fmaxf(m, s);
        float sc = __expf(m - nm);   // first iter: exp(-inf) = 0
        float pe = __expf(s - nm);
        l = l * sc + pe;
        float vx[VEC];
        {
            const float* vp = Vp + (size_t)cidx * D + lane * VEC;
            if (VEC == 4) { float4 t = *(const float4*)vp; vx[0]=t.x; vx[1]=t.y; vx[2]=t.z; vx[3]=t.w; }
            else          { float2 t = *(const float2*)vp; vx[0]=t.x; vx[1]=t.y; }
        }
#pragma unroll
        for (int v = 0; v < VEC; v++) acc[v] = acc[v] * sc + pe * vx[v];
        m = nm;
    }
    float inv = beta / (l + 1e-16f);
    float* op = out + (size_t)gw * D + lane * VEC;
    if (accumulate) {
#pragma unroll
        for (int v = 0; v < VEC; v++) op[v] += acc[v] * inv;
    } else {
        if (VEC == 4) {
            float4 o; o.x = acc[0]*inv; o.y = acc[1]*inv; o.z = acc[2]*inv; o.w = acc[3]*inv;
            *(float4*)op = o;
        } else {
            float2 o; o.x = acc[0]*inv; o.y = acc[1]*inv;
            *(float2*)op = o;
        }
    }
}

// ---------------- elementwise ----------------
__global__ void elu_kernel(int n) {
    int i = blockIdx.x * blockDim.x + threadIdx.x;
    if (i < n) {
        float v = g_H[i];
        g_H[i] = v > 0.f ? v : expm1f(v);
    }
}

__global__ void logsoftmax_kernel(float* __restrict__ o, int n) {
    int gw = (blockIdx.x * blockDim.x + threadIdx.x) >> 5;
    if (gw >= n) return;
    int lane = threadIdx.x & 31;
    float2 v = *(float2*)(o + (size_t)gw * 64 + lane * 2);
    float m = fmaxf(v.x, v.y);
#pragma unroll
    for (int off = 16; off; off >>= 1) m = fmaxf(m, __shfl_xor_sync(0xffffffffu, m, off));
    float s = expf(v.x - m) + expf(v.y - m);
#pragma unroll
    for (int off = 16; off; off >>= 1) s += __shfl_xor_sync(0xffffffffu, s, off);
    float lg = m + logf(s);
    v.x -= lg; v.y -= lg;
    *(float2*)(o + (size_t)gw * 64 + lane * 2) = v;
}

// ---------------- launch ----------------
extern "C" void kernel_launch(void* const* d_in, const int* in_sizes, int n_in,
                              void* d_out, int out_size) {
    const float* x   = (const float*)d_in[0];
    const int* edge0 = (const int*)d_in[1];
    const int* edge1 = (const int*)d_in[2];
    const float* W0q = (const float*)d_in[3];
    const float* W0k = (const float*)d_in[4];
    const float* W0v = (const float*)d_in[5];
    const float* b0q = (const float*)d_in[6];
    const float* b0k = (const float*)d_in[7];
    const float* b0v = (const float*)d_in[8];
    const float* W1q = (const float*)d_in[9];
    const float* W1k = (const float*)d_in[10];
    const float* W1v = (const float*)d_in[11];
    const float* b1q = (const float*)d_in[12];
    const float* b1k = (const float*)d_in[13];
    const float* b1v = (const float*)d_in[14];
    float* out = (float*)d_out;

    int M = in_sizes[0] / D_IN;   // 50000
    int E = in_sizes[1] / 2;      // 400000

    const int* edges[2] = {edge0, edge1};
    int nb = (M + 255) / 256;
    int eb = (E + 255) / 256;
    for (int hop = 0; hop < 2; hop++) {
        zero_deg_kernel<<<nb, 256>>>(M);
        count_deg_kernel<<<eb, 256>>>(edges[hop], E);
        scan_kernel<<<1, 1024>>>(hop, M);
        cursor_kernel<<<nb, 256>>>(hop, M);
        scatter_kernel<<<eb, 256>>>(edges[hop], edges[hop] + E, E, hop);
    }

    // layer 0: 4 combos x {q,k,v} in one launch
    dim3 g0((M + 127) / 128, 1, 12);
    qkv_gemm_kernel<0, 128, 128, 16, 8, 8><<<g0, 256>>>(x, W0q, W0k, W0v, b0q, b0k, b0v, M, D_IN);

    const float rsq32 = 0.17677669529663687f;  // 1/sqrt(32)
    int ab = (M * 32 + 255) / 256;
    // combo = head*2 + hop ; beta = 1.0 for hop0, 0.5/2 = 0.25 for hop1
    attn_kernel<4><<<ab, 256>>>(0, 0, 1.0f,  rsq32, 0, nullptr, 0, M);
    attn_kernel<4><<<ab, 256>>>(1, 1, 0.25f, rsq32, 1, nullptr, 0, M);
    attn_kernel<4><<<ab, 256>>>(2, 0, 1.0f,  rsq32, 1, nullptr, 0, M);
    attn_kernel<4><<<ab, 256>>>(3, 1, 0.25f, rsq32, 1, nullptr, 0, M);

    elu_kernel<<<(M * D_HID + 255) / 256, 256>>>(M * D_HID);

    // layer 1: 2 combos x {q,k,v}
    dim3 g1((M + 127) / 128, 1, 6);
    qkv_gemm_kernel<1, 128, 64, 16, 8, 4><<<g1, 256>>>(x, W1q, W1k, W1v, b1q, b1k, b1v, M, D_HID);

    const float rsq16 = 0.25f;  // 1/sqrt(16)
    attn_kernel<2><<<ab, 256>>>(0, 0, 1.0f,  rsq16, 0, out, 1, M);
    attn_kernel<2><<<ab, 256>>>(1, 1, 0.25f, rsq16, 1, out, 1, M);

    logsoftmax_kernel<<<ab, 256>>>(out, M);
}